// round 17
// baseline (speedup 1.0000x reference)
#include <cuda_runtime.h>
#include <cuda_bf16.h>
#include <cuda_fp16.h>
#include <cstdint>

#define BB 2
#define LL 4096
#define EMBED 2048
#define DIN 4096
#define NH 32
#define HD 128
#define DS 64
#define CONVDIM 4224   // DIN + 2*DS
#define DPROJ 8352     // 2*DIN + 2*DS + NH
#define CHUNK 256
#define NCH 16         // LL / CHUNK
#define NBC (BB*NCH)   // 32

// ------------------- scratch (device globals; no cudaMalloc allowed) ---------
__device__ float g_zx[(size_t)BB*LL*DPROJ];        // in_proj output
__device__ float g_xbc[(size_t)BB*LL*CONVDIM];     // conv+silu output
__device__ float g_dt[BB*LL*NH];                   // softplus(dt)
__device__ float g_a[NBC*CHUNK*NH];                // cumsum(dA) per chunk
__device__ float g_alast[NBC*NH];
__device__ float g_scores[(size_t)NBC*CHUNK*CHUNK];
__device__ float g_states[(size_t)NBC*NH*HD*DS];   // [b,c,h,p,n]
__device__ float g_prev[(size_t)NBC*NH*HD*DS];     // state entering chunk c

// fp16 hi/lo (activations) and fp16 (weights) buffers
__device__ __half g_uh[(size_t)BB*LL*EMBED];
__device__ __half g_ul[(size_t)BB*LL*EMBED];
__device__ __half g_w1h[(size_t)DPROJ*EMBED];
__device__ __half g_w2h[(size_t)EMBED*DIN];
__device__ __half g_ynh[(size_t)BB*LL*DIN];
__device__ __half g_ynl[(size_t)BB*LL*DIN];

// ------------------- PTX helpers (sm_80-era: valid on base sm_103 target) ----
__device__ __forceinline__ uint32_t s2u(const void* p) {
    uint32_t a;
    asm("{ .reg .u64 t; cvta.to.shared.u64 t, %1; cvt.u32.u64 %0, t; }" : "=r"(a) : "l"(p));
    return a;
}
__device__ __forceinline__ void cpasync16(uint32_t s, const void* g, int srcsize) {
    asm volatile("cp.async.cg.shared.global [%0], [%1], 16, %2;"
                 :: "r"(s), "l"(g), "r"(srcsize));
}
__device__ __forceinline__ void cpcommit() {
    asm volatile("cp.async.commit_group;" ::: "memory");
}
template <int N>
__device__ __forceinline__ void cpwait() {
    asm volatile("cp.async.wait_group %0;" :: "n"(N) : "memory");
}
__device__ __forceinline__ void ldsm4(uint32_t* r, uint32_t addr) {
    asm volatile("ldmatrix.sync.aligned.m8n8.x4.shared.b16 {%0,%1,%2,%3}, [%4];"
                 : "=r"(r[0]), "=r"(r[1]), "=r"(r[2]), "=r"(r[3]) : "r"(addr));
}
__device__ __forceinline__ void mma16816h(float* c, const uint32_t* a, const uint32_t* b) {
    asm volatile(
        "mma.sync.aligned.m16n8k16.row.col.f32.f16.f16.f32 "
        "{%0,%1,%2,%3},{%4,%5,%6,%7},{%8,%9},{%0,%1,%2,%3};"
        : "+f"(c[0]), "+f"(c[1]), "+f"(c[2]), "+f"(c[3])
        : "r"(a[0]), "r"(a[1]), "r"(a[2]), "r"(a[3]), "r"(b[0]), "r"(b[1]));
}
__device__ __forceinline__ void mma_tf32(float* d, const uint32_t* a, const uint32_t* b) {
    asm volatile(
        "mma.sync.aligned.m16n8k8.row.col.f32.tf32.tf32.f32 "
        "{%0,%1,%2,%3},{%4,%5,%6,%7},{%8,%9},{%0,%1,%2,%3};"
        : "+f"(d[0]), "+f"(d[1]), "+f"(d[2]), "+f"(d[3])
        : "r"(a[0]), "r"(a[1]), "r"(a[2]), "r"(a[3]), "r"(b[0]), "r"(b[1]));
}
__device__ __forceinline__ uint32_t f2tf(float x) {
    uint32_t r; asm("cvt.rna.tf32.f32 %0, %1;" : "=r"(r) : "f"(x)); return r;
}

// ------------------- fp32 -> fp16 hi/lo split (activations) ------------------
__global__ void split2h(const float* __restrict__ s, __half* __restrict__ hi,
                        __half* __restrict__ lo, int n4)
{
    int i = blockIdx.x * 256 + threadIdx.x;
    if (i >= n4) return;
    float4 v = ((const float4*)s)[i];
    __half h0 = __float2half(v.x), h1 = __float2half(v.y);
    __half h2 = __float2half(v.z), h3 = __float2half(v.w);
    __half2* H = (__half2*)hi;
    __half2* L = (__half2*)lo;
    H[i*2+0] = __halves2half2(h0, h1);
    H[i*2+1] = __halves2half2(h2, h3);
    L[i*2+0] = __halves2half2(__float2half(v.x - __half2float(h0)),
                              __float2half(v.y - __half2float(h1)));
    L[i*2+1] = __halves2half2(__float2half(v.z - __half2float(h2)),
                              __float2half(v.w - __half2float(h3)));
}

// ------------------- fp32 -> fp16 convert (weights) --------------------------
__global__ void cvt_h(const float* __restrict__ s, __half* __restrict__ d, int n4)
{
    int i = blockIdx.x * 256 + threadIdx.x;
    if (i >= n4) return;
    float4 v = ((const float4*)s)[i];
    __half2* D = (__half2*)d;
    D[i*2+0] = __halves2half2(__float2half(v.x), __float2half(v.y));
    D[i*2+1] = __halves2half2(__float2half(v.z), __float2half(v.w));
}

// ------------- HMMA fp16x2 GEMM: C[M,N] = (Ah+Al)[M,K] @ Bh[N,K]^T -----------
// CTA tile 128x256, BK=64, 512 threads = 16 warps (4m x 4n), warp tile 32x64.
// MMA/ldsm ratio 4.0. cp.async.cg. 2 stages (147KB), 1 CTA/SM (16 warps).
#define HBM 128
#define HBN 256
#define HBK 64
#define HLD 72
#define HAB (128*HLD*2)              // A matrix bytes/stage (18432)
#define HBB (256*HLD*2)              // B matrix bytes/stage (36864)
#define HSTAGEB (2*HAB + HBB)        // 73728

__global__ __launch_bounds__(512) void hgemm2(
    int M, int N, int K,
    const __half* __restrict__ Ah, const __half* __restrict__ Al,
    const __half* __restrict__ Bh, float* __restrict__ C)
{
    extern __shared__ char smem[];
    const int tid = threadIdx.x;
    const int lane = tid & 31, wid = tid >> 5;
    const int wm = wid & 3, wn = wid >> 2;   // 4m x 4n, warp tile 32(m) x 64(n)
    const int bm = blockIdx.y * HBM, bn = blockIdx.x * HBN;
    const uint32_t sbase = s2u(smem);

    const int arow = lane & 15, akoff = (lane >> 4) << 3;
    const int bnl = (lane & 7) + ((lane >> 4) << 3);
    const int bkl = ((lane >> 3) & 1) << 3;

    float acc[2][8][4];
    #pragma unroll
    for (int mt = 0; mt < 2; mt++)
        #pragma unroll
        for (int nt = 0; nt < 8; nt++)
            #pragma unroll
            for (int i = 0; i < 4; i++) acc[mt][nt][i] = 0.f;

    const int nk = K / HBK;

    // ---- stage loader: A 1024 chunks x2 (hi/lo), B 2048 chunks ----
    auto load_stage = [&](int st, int k0) {
        uint32_t sb = sbase + st * HSTAGEB;
        #pragma unroll
        for (int i = 0; i < 2; i++) {
            int chunk = tid + i * 512;
            int row = chunk >> 3, c = chunk & 7;
            uint32_t so = (uint32_t)(row * HLD + c * 8) * 2;
            size_t ga = (size_t)(bm + row) * K + k0 + c * 8;
            cpasync16(sb + so,       Ah + ga, 16);
            cpasync16(sb + HAB + so, Al + ga, 16);
        }
        #pragma unroll
        for (int i = 0; i < 4; i++) {
            int chunk = tid + i * 512;
            int row = chunk >> 3, c = chunk & 7;
            uint32_t so = (uint32_t)(row * HLD + c * 8) * 2;
            int brow = bn + row;
            int sz = (brow < N) ? 16 : 0;
            int bcl = (brow < N) ? brow : 0;
            size_t gb = (size_t)bcl * K + k0 + c * 8;
            cpasync16(sb + 2*HAB + so, Bh + gb, sz);
        }
        cpcommit();
    };

    load_stage(0, 0);

    for (int kt = 0; kt < nk; ++kt) {
        if (kt + 1 < nk) {
            load_stage((kt + 1) & 1, (kt + 1) * HBK);
            cpwait<1>();
        } else {
            cpwait<0>();
        }
        __syncthreads();

        uint32_t sb = sbase + (kt & 1) * HSTAGEB;
        uint32_t sAh = sb, sAl = sb + HAB, sBh = sb + 2*HAB;

        #pragma unroll
        for (int kh = 0; kh < 4; kh++) {
            int k = kh * 16;
            uint32_t bfh[4][4];
            #pragma unroll
            for (int ntp = 0; ntp < 4; ntp++) {
                uint32_t off = (uint32_t)((wn * 64 + ntp * 16 + bnl) * HLD + k + bkl) * 2;
                ldsm4(bfh[ntp], sBh + off);
            }
            #pragma unroll
            for (int mt = 0; mt < 2; mt++) {
                uint32_t aoff = (uint32_t)((wm * 32 + mt * 16 + arow) * HLD + k + akoff) * 2;
                uint32_t af[4];
                ldsm4(af, sAh + aoff);
                #pragma unroll
                for (int nt = 0; nt < 8; nt++)
                    mma16816h(acc[mt][nt], af, &bfh[nt >> 1][(nt & 1) * 2]);
                ldsm4(af, sAl + aoff);
                #pragma unroll
                for (int nt = 0; nt < 8; nt++)
                    mma16816h(acc[mt][nt], af, &bfh[nt >> 1][(nt & 1) * 2]);
            }
        }
        __syncthreads();
    }

    #pragma unroll
    for (int mt = 0; mt < 2; mt++) {
        int row0 = bm + wm * 32 + mt * 16 + (lane >> 2);
        #pragma unroll
        for (int nt = 0; nt < 8; nt++) {
            int col = bn + wn * 64 + nt * 8 + (lane & 3) * 2;
            if (col < N) {
                *(float2*)&C[(size_t)row0 * N + col] =
                    make_float2(acc[mt][nt][0], acc[mt][nt][1]);
                *(float2*)&C[(size_t)(row0 + 8) * N + col] =
                    make_float2(acc[mt][nt][2], acc[mt][nt][3]);
            }
        }
    }
}

// --------- depthwise causal conv (k=4) + silu, smem-tiled (reads 1x) ---------
__global__ __launch_bounds__(256) void conv_silu_k(const float* __restrict__ cw,
                                                   const float* __restrict__ cb)
{
    int ct = blockIdx.x;           // 0..65  (CONVDIM/64)
    int lt = blockIdx.y;           // 0..31  (LL/128)
    int b  = blockIdx.z;
    int c0 = ct * 64, l0 = lt * 128;
    __shared__ float tile[131][64];
    int tid = threadIdx.x;
    int tc = tid & 63, tg = tid >> 6;   // channel-in-tile, group 0..3
    for (int r = tg; r < 131; r += 4) {
        int l = l0 + r - 3;
        float v = 0.f;
        if (l >= 0) v = g_zx[(size_t)(b * LL + l) * DPROJ + DIN + c0 + tc];
        tile[r][tc] = v;
    }
    __syncthreads();
    int ch = c0 + tc;
    float w0 = cw[ch * 4 + 0], w1 = cw[ch * 4 + 1];
    float w2 = cw[ch * 4 + 2], w3 = cw[ch * 4 + 3];
    float bias = cb[ch];
    #pragma unroll 4
    for (int i = 0; i < 32; i++) {
        int lr = tg * 32 + i;
        float acc = bias + tile[lr][tc] * w0 + tile[lr + 1][tc] * w1
                  + tile[lr + 2][tc] * w2 + tile[lr + 3][tc] * w3;
        g_xbc[(size_t)(b * LL + l0 + lr) * CONVDIM + ch] = acc / (1.f + __expf(-acc));
    }
}

// ------------------- per-chunk cumsum of dA (fused softplus + warp scan) -----
__global__ void cumsum_k(const float* __restrict__ A_log, const float* __restrict__ dt_bias)
{
    int bch = blockIdx.x;            // bc*NH + h
    int h = bch & 31, bc = bch >> 5;
    int b = bc / NCH, c = bc % NCH;
    int t = threadIdx.x;             // 32
    float Ah = -__expf(A_log[h]);
    float bias = dt_bias[h];
    size_t row0 = (size_t)(b * LL + c * CHUNK) + t * 8;
    float v[8];
    #pragma unroll
    for (int j = 0; j < 8; j++) {
        float x = g_zx[(row0 + j) * DPROJ + DIN + CONVDIM + h] + bias;
        float sp = (x > 20.f) ? x : log1pf(__expf(x));
        g_dt[(row0 + j) * NH + h] = sp;
        v[j] = sp * Ah;
    }
    float loc = 0.f;
    #pragma unroll
    for (int j = 0; j < 8; j++) { loc += v[j]; v[j] = loc; }
    float pre = loc;
    #pragma unroll
    for (int o = 1; o < 32; o <<= 1) {
        float nv = __shfl_up_sync(0xffffffffu, pre, o);
        if (t >= o) pre += nv;
    }
    pre -= loc;   // exclusive prefix
    #pragma unroll
    for (int j = 0; j < 8; j++) g_a[(bc * CHUNK + t * 8 + j) * NH + h] = pre + v[j];
    if (t == 31) g_alast[bc * NH + h] = pre + loc;
}

// ---------- scores = C @ B^T per chunk (lower tiles, tf32 MMA) ---------------
__global__ __launch_bounds__(256) void scores_k()
{
    int jt = blockIdx.x, it = blockIdx.y, bc = blockIdx.z;
    if (jt > it) return;
    int b = bc / NCH, c = bc % NCH;
    __shared__ float CtT[64 * 72];   // [n][r] k-major
    __shared__ float BtT[64 * 72];
    int tid = threadIdx.x;
    const int lane = tid & 31, wid = tid >> 5;
    const int gid = lane >> 2, tig = lane & 3;
    const int wm = wid >> 2, wn = wid & 3;   // 2m x 4n
    for (int t = tid; t < 64 * 64; t += 256) {
        int r = t >> 6, n = t & 63;
        int rowC = b * LL + c * CHUNK + it * 64 + r;
        int rowB = b * LL + c * CHUNK + jt * 64 + r;
        CtT[n * 72 + r] = g_xbc[(size_t)rowC * CONVDIM + DIN + DS + n];
        BtT[n * 72 + r] = g_xbc[(size_t)rowB * CONVDIM + DIN + n];
    }
    __syncthreads();
    float acc[2][2][4];
    #pragma unroll
    for (int mt = 0; mt < 2; mt++)
        #pragma unroll
        for (int nf = 0; nf < 2; nf++)
            #pragma unroll
            for (int i = 0; i < 4; i++) acc[mt][nf][i] = 0.f;
    #pragma unroll
    for (int ks = 0; ks < 8; ks++) {
        int k8 = ks * 8;
        uint32_t bfr[2][2];
        #pragma unroll
        for (int nf = 0; nf < 2; nf++) {
            int col = wn * 16 + nf * 8 + gid;
            bfr[nf][0] = f2tf(BtT[(k8 + tig)     * 72 + col]);
            bfr[nf][1] = f2tf(BtT[(k8 + tig + 4) * 72 + col]);
        }
        #pragma unroll
        for (int mt = 0; mt < 2; mt++) {
            int r0 = wm * 32 + mt * 16 + gid;
            uint32_t afr[4];
            afr[0] = f2tf(CtT[(k8 + tig)     * 72 + r0]);
            afr[1] = f2tf(CtT[(k8 + tig)     * 72 + r0 + 8]);
            afr[2] = f2tf(CtT[(k8 + tig + 4) * 72 + r0]);
            afr[3] = f2tf(CtT[(k8 + tig + 4) * 72 + r0 + 8]);
            #pragma unroll
            for (int nf = 0; nf < 2; nf++)
                mma_tf32(acc[mt][nf], afr, bfr[nf]);
        }
    }
    #pragma unroll
    for (int mt = 0; mt < 2; mt++)
        #pragma unroll
        for (int hf = 0; hf < 2; hf++) {
            int r = wm * 32 + mt * 16 + hf * 8 + gid;
            #pragma unroll
            for (int nf = 0; nf < 2; nf++) {
                int n = wn * 16 + nf * 8 + 2 * tig;
                *(float2*)&g_scores[((size_t)bc << 16) + (it * 64 + r) * 256 + jt * 64 + n] =
                    make_float2(acc[mt][nf][hf * 2], acc[mt][nf][hf * 2 + 1]);
            }
        }
}

// ------------- per-chunk states[h,p,n] = X^T @ Bco  (tf32 MMA) ---------------
__global__ __launch_bounds__(256) void states_k()
{
    int bch = blockIdx.x;              // bc*NH + h
    int h = bch % NH, bc = bch / NH;
    int b = bc / NCH, c = bc % NCH;
    __shared__ float sh[6688];
    float* Xs   = sh;                  // 32 x 136 (q-major, p cols)
    float* Bs   = sh + 4352;           // 32 x 72  (q-major, n cols)
    float* coef = sh + 6656;           // 32
    int tid = threadIdx.x;
    const int lane = tid & 31, wid = tid >> 5;
    const int gid = lane >> 2, tig = lane & 3;
    const int wm = wid & 3, wn = wid >> 2;    // 4m x 2n
    float alast = g_alast[bc * NH + h];
    float acc[2][4][4];
    #pragma unroll
    for (int mt = 0; mt < 2; mt++)
        #pragma unroll
        for (int nt = 0; nt < 4; nt++)
            #pragma unroll
            for (int i = 0; i < 4; i++) acc[mt][nt][i] = 0.f;

    for (int q0 = 0; q0 < CHUNK; q0 += 32) {
        __syncthreads();
        if (tid < 32) {
            int gq = q0 + tid;
            float aq = g_a[(bc * CHUNK + gq) * NH + h];
            float dtq = g_dt[(size_t)(b * LL + c * CHUNK + gq) * NH + h];
            coef[tid] = dtq * __expf(alast - aq);
        }
        #pragma unroll
        for (int t = 0; t < 16; t++) {
            int idx = tid + t * 256;
            int q = idx >> 7, p = idx & 127;
            Xs[q * 136 + p] = g_xbc[(size_t)(b * LL + c * CHUNK + q0 + q) * CONVDIM + h * HD + p];
        }
        __syncthreads();
        #pragma unroll
        for (int t = 0; t < 8; t++) {
            int idx = tid + t * 256;
            int q = idx >> 6, n = idx & 63;
            Bs[q * 72 + n] = g_xbc[(size_t)(b * LL + c * CHUNK + q0 + q) * CONVDIM + DIN + n] * coef[q];
        }
        __syncthreads();
        #pragma unroll
        for (int ks = 0; ks < 4; ks++) {
            int k8 = ks * 8;
            uint32_t bfr[4][2];
            #pragma unroll
            for (int ntf = 0; ntf < 4; ntf++) {
                int nb = wn * 32 + ntf * 8 + gid;
                bfr[ntf][0] = f2tf(Bs[(k8 + tig)     * 72 + nb]);
                bfr[ntf][1] = f2tf(Bs[(k8 + tig + 4) * 72 + nb]);
            }
            #pragma unroll
            for (int mt = 0; mt < 2; mt++) {
                int r0 = wm * 32 + mt * 16 + gid;
                uint32_t afr[4];
                afr[0] = f2tf(Xs[(k8 + tig)     * 136 + r0]);
                afr[1] = f2tf(Xs[(k8 + tig)     * 136 + r0 + 8]);
                afr[2] = f2tf(Xs[(k8 + tig + 4) * 136 + r0]);
                afr[3] = f2tf(Xs[(k8 + tig + 4) * 136 + r0 + 8]);
                #pragma unroll
                for (int ntf = 0; ntf < 4; ntf++)
                    mma_tf32(acc[mt][ntf], afr, bfr[ntf]);
            }
        }
    }
    size_t base = (size_t)bch * HD * DS;
    #pragma unroll
    for (int mt = 0; mt < 2; mt++)
        #pragma unroll
        for (int hf = 0; hf < 2; hf++) {
            int p = wm * 32 + mt * 16 + hf * 8 + gid;
            #pragma unroll
            for (int ntf = 0; ntf < 4; ntf++) {
                int n = wn * 32 + ntf * 8 + 2 * tig;
                *(float2*)&g_states[base + (size_t)p * DS + n] =
                    make_float2(acc[mt][ntf][hf * 2], acc[mt][ntf][hf * 2 + 1]);
            }
        }
}

// ------------------- sequential inter-chunk scan (split over 16 slices) ------
__global__ void scan_k()
{
    int bh = blockIdx.x;            // b*NH + h
    int b = bh >> 5, h = bh & 31;
    int e = blockIdx.y * 512 + threadIdx.x;   // element in HD*DS plane
    float s = 0.f;
    for (int c = 0; c < NCH; c++) {
        int bc = b * NCH + c;
        float dec = __expf(g_alast[bc * NH + h]);
        size_t base = (size_t)(bc * NH + h) * HD * DS;
        g_prev[base + e] = s;
        s = s * dec + g_states[base + e];
    }
}

// ------ y = intra + inter + D*x (tf32 MMA) + fused gate + per-head RMS -------
__global__ __launch_bounds__(256) void ych_k(const float* __restrict__ D_skip,
                                             const float* __restrict__ norm_w)
{
    int it = blockIdx.x;   // 0..3 (64-row tile)
    int h  = blockIdx.y;   // 0..31
    int bc = blockIdx.z;   // 0..31
    int b = bc / NCH, c = bc % NCH;
    __shared__ float sh[9088];
    float* ai    = sh;            // 64
    float* er    = sh + 64;       // 64
    float* Ab    = sh + 128;      // 4352: Wt[64][36] (p1) / Ct[64][68] (p2)
    float* Bb    = sh + 4480;     // 4352: Xt[32][136] (p1) / prevT[32][136] (p2)
    float* ssbuf = sh + 8832;     // 64*4
    int tid = threadIdx.x;
    const int lane = tid & 31, wid = tid >> 5;
    const int gid = lane >> 2, tig = lane & 3;
    const int wm = wid >> 2, wn = wid & 3;     // 2m x 4n
    int row0 = b * LL + c * CHUNK;
    float aref = g_a[(bc * CHUNK + it * 64) * NH + h];
    if (tid < 64) {
        float av = g_a[(bc * CHUNK + it * 64 + tid) * NH + h];
        ai[tid] = av;
        er[tid] = __expf(av - aref);
    }
    float accA[2][4][4], accB[2][4][4];
    #pragma unroll
    for (int mt = 0; mt < 2; mt++)
        #pragma unroll
        for (int nt = 0; nt < 4; nt++)
            #pragma unroll
            for (int i = 0; i < 4; i++) { accA[mt][nt][i] = 0.f; accB[mt][nt][i] = 0.f; }
    __syncthreads();

    // ================== phase 1: intra (K tiles of 32) ==================
    int jtmax = 2 * it + 1;
    for (int jt = 0; jt <= jtmax; jt++) {
        int j0 = jt * 32;
        if (jt < 2 * it) {
            int j = tid & 31;
            int gj = j0 + j;
            float ec = __expf(aref - g_a[(bc * CHUNK + gj) * NH + h]) *
                       g_dt[(size_t)(row0 + gj) * NH + h];
            #pragma unroll
            for (int t = 0; t < 8; t++) {
                int i = (tid >> 5) + t * 8;
                int gi = it * 64 + i;
                Ab[i * 36 + j] =
                    g_scores[((size_t)bc << 16) + gi * 256 + gj] * er[i] * ec;
            }
        } else {
            #pragma unroll
            for (int t = 0; t < 8; t++) {
                int idx = tid + t * 256;
                int i = idx >> 5, j = idx & 31;
                int gi = it * 64 + i, gj = j0 + j;
                float w = 0.f;
                if (gj <= gi) {
                    float aj = g_a[(bc * CHUNK + gj) * NH + h];
                    float dtj = g_dt[(size_t)(row0 + gj) * NH + h];
                    w = g_scores[((size_t)bc << 16) + gi * 256 + gj] * __expf(ai[i] - aj) * dtj;
                }
                Ab[i * 36 + j] = w;
            }
        }
        #pragma unroll
        for (int t = 0; t < 16; t++) {
            int idx = tid + t * 256;
            int j = idx >> 7, p = idx & 127;
            Bb[j * 136 + p] = g_xbc[(size_t)(row0 + j0 + j) * CONVDIM + h * HD + p];
        }
        __syncthreads();
        #pragma unroll
        for (int ks = 0; ks < 4; ks++) {
            uint32_t bfr[4][2];
            #pragma unroll
            for (int ntf = 0; ntf < 4; ntf++) {
                bfr[ntf][0] = f2tf(Bb[(ks*8 + tig)     * 136 + wn*32 + ntf*8 + gid]);
                bfr[ntf][1] = f2tf(Bb[(ks*8 + tig + 4) * 136 + wn*32 + ntf*8 + gid]);
            }
            #pragma unroll
            for (int mt = 0; mt < 2; mt++) {
                int r0 = wm*32 + mt*16 + gid;
                uint32_t afr[4];
                afr[0] = f2tf(Ab[ r0      * 36 + ks*8 + tig]);
                afr[1] = f2tf(Ab[(r0 + 8) * 36 + ks*8 + tig]);
                afr[2] = f2tf(Ab[ r0      * 36 + ks*8 + tig + 4]);
                afr[3] = f2tf(Ab[(r0 + 8) * 36 + ks*8 + tig + 4]);
                #pragma unroll
                for (int ntf = 0; ntf < 4; ntf++)
                    mma_tf32(accA[mt][ntf], afr, bfr[ntf]);
            }
        }
        __syncthreads();
    }

    // ================== phase 2: inter (K = 64, 2 tiles) ==================
    #pragma unroll
    for (int t = 0; t < 16; t++) {
        int idx = tid + t * 256;
        int i = idx >> 6, n = idx & 63;
        Ab[i * 68 + n] = g_xbc[(size_t)(row0 + it * 64 + i) * CONVDIM + DIN + DS + n];
    }
    size_t pbase = (size_t)(bc * NH + h) * HD * DS;
    for (int nt = 0; nt < 2; nt++) {
        int n0 = nt * 32;
        #pragma unroll
        for (int t = 0; t < 16; t++) {
            int idx = tid + t * 256;
            int p = idx >> 5, n = idx & 31;
            Bb[n * 136 + p] = g_prev[pbase + (size_t)p * DS + n0 + n];
        }
        __syncthreads();
        #pragma unroll
        for (int ks = 0; ks < 4; ks++) {
            uint32_t bfr[4][2];
            #pragma unroll
            for (int ntf = 0; ntf < 4; ntf++) {
                bfr[ntf][0] = f2tf(Bb[(ks*8 + tig)     * 136 + wn*32 + ntf*8 + gid]);
                bfr[ntf][1] = f2tf(Bb[(ks*8 + tig + 4) * 136 + wn*32 + ntf*8 + gid]);
            }
            #pragma unroll
            for (int mt = 0; mt < 2; mt++) {
                int r0 = wm*32 + mt*16 + gid;
                uint32_t afr[4];
                afr[0] = f2tf(Ab[ r0      * 68 + n0 + ks*8 + tig]);
                afr[1] = f2tf(Ab[(r0 + 8) * 68 + n0 + ks*8 + tig]);
                afr[2] = f2tf(Ab[ r0      * 68 + n0 + ks*8 + tig + 4]);
                afr[3] = f2tf(Ab[(r0 + 8) * 68 + n0 + ks*8 + tig + 4]);
                #pragma unroll
                for (int ntf = 0; ntf < 4; ntf++)
                    mma_tf32(accB[mt][ntf], afr, bfr[ntf]);
            }
        }
        __syncthreads();
    }

    // ====== epilogue: combine + D skip + gate + RMS (mma layout) ======
    float Dh = D_skip[h];
    #pragma unroll
    for (int mt = 0; mt < 2; mt++) {
        #pragma unroll
        for (int hf = 0; hf < 2; hf++) {
            int rl = wm*32 + mt*16 + hf*8 + gid;
            int gi = it * 64 + rl;
            float ea = __expf(ai[rl]);
            float ss = 0.f;
            #pragma unroll
            for (int ntf = 0; ntf < 4; ntf++) {
                int col = wn*32 + ntf*8 + 2*tig;
                float2 xv = *(const float2*)&g_xbc[(size_t)(row0 + gi) * CONVDIM + h * HD + col];
                float2 zv = *(const float2*)&g_zx[(size_t)(row0 + gi) * DPROJ + h * HD + col];
                float o0 = accA[mt][ntf][hf*2+0] + ea * accB[mt][ntf][hf*2+0] + Dh * xv.x;
                float o1 = accA[mt][ntf][hf*2+1] + ea * accB[mt][ntf][hf*2+1] + Dh * xv.y;
                float v0 = o0 / (1.f + __expf(-zv.x));
                float v1 = o1 / (1.f + __expf(-zv.y));
                accA[mt][ntf][hf*2+0] = v0;
                accA[mt][ntf][hf*2+1] = v1;
                ss += v0 * v0 + v1 * v1;
            }
            ss += __shfl_xor_sync(0xffffffffu, ss, 1);
            ss += __shfl_xor_sync(0xffffffffu, ss, 2);
            if (tig == 0) ssbuf[rl * 4 + wn] = ss;
        }
    }
    __syncthreads();
    #pragma unroll
    for (int mt = 0; mt < 2; mt++) {
        #pragma unroll
        for (int hf = 0; hf < 2; hf++) {
            int rl = wm*32 + mt*16 + hf*8 + gid;
            int gi = it * 64 + rl;
            float tot = ssbuf[rl*4+0] + ssbuf[rl*4+1] + ssbuf[rl*4+2] + ssbuf[rl*4+3];
            float inv = rsqrtf(tot * (1.f / HD) + 1e-6f);
            #pragma unroll
            for (int ntf = 0; ntf < 4; ntf++) {
                int col = wn*32 + ntf*8 + 2*tig;
                float2 nw = *(const float2*)&norm_w[h * HD + col];
                float r0 = accA[mt][ntf][hf*2+0] * inv * nw.x;
                float r1 = accA[mt][ntf][hf*2+1] * inv * nw.y;
                size_t oi = (size_t)(row0 + gi) * DIN + h * HD + col;
                __half h0 = __float2half(r0), h1 = __float2half(r1);
                *(__half2*)&g_ynh[oi] = __halves2half2(h0, h1);
                *(__half2*)&g_ynl[oi] = __halves2half2(
                    __float2half(r0 - __half2float(h0)),
                    __float2half(r1 - __half2float(h1)));
            }
        }
    }
}

// ------------------- launch ---------------------------------------------------
extern "C" void kernel_launch(void* const* d_in, const int* in_sizes, int n_in,
                              void* d_out, int out_size)
{
    const float* u         = (const float*)d_in[0];
    const float* in_proj_w = (const float*)d_in[1];
    const float* conv_w    = (const float*)d_in[2];
    const float* conv_b    = (const float*)d_in[3];
    const float* A_log     = (const float*)d_in[4];
    const float* dt_bias   = (const float*)d_in[5];
    const float* D_skip    = (const float*)d_in[6];
    const float* norm_w    = (const float*)d_in[7];
    const float* o_proj_w  = (const float*)d_in[8];
    float* out = (float*)d_out;

    float* zx = nullptr;
    cudaGetSymbolAddress((void**)&zx, g_zx);
    __half *uh, *ul, *w1h, *w2h, *ynh, *ynl;
    cudaGetSymbolAddress((void**)&uh,  g_uh);
    cudaGetSymbolAddress((void**)&ul,  g_ul);
    cudaGetSymbolAddress((void**)&w1h, g_w1h);
    cudaGetSymbolAddress((void**)&w2h, g_w2h);
    cudaGetSymbolAddress((void**)&ynh, g_ynh);
    cudaGetSymbolAddress((void**)&ynl, g_ynl);

    const int SMEM_GEMM = 2 * HSTAGEB;   // 147456
    cudaFuncSetAttribute(hgemm2, cudaFuncAttributeMaxDynamicSharedMemorySize, SMEM_GEMM);

    // Side streams + events (created once; resources only).
    static cudaStream_t sW2 = nullptr, sCS = nullptr, sSC = nullptr;
    static cudaEvent_t evStart, evW2, evZX, evCum, evXBC, evScores;
    if (!sW2) {
        cudaStreamCreateWithFlags(&sW2, cudaStreamNonBlocking);
        cudaStreamCreateWithFlags(&sCS, cudaStreamNonBlocking);
        cudaStreamCreateWithFlags(&sSC, cudaStreamNonBlocking);
        cudaEventCreateWithFlags(&evStart,  cudaEventDisableTiming);
        cudaEventCreateWithFlags(&evW2,     cudaEventDisableTiming);
        cudaEventCreateWithFlags(&evZX,     cudaEventDisableTiming);
        cudaEventCreateWithFlags(&evCum,    cudaEventDisableTiming);
        cudaEventCreateWithFlags(&evXBC,    cudaEventDisableTiming);
        cudaEventCreateWithFlags(&evScores, cudaEventDisableTiming);
    }

    const int M = BB * LL;   // 8192

    // fork point for the w2 convert (needed only by the final o_proj)
    cudaEventRecord(evStart, 0);
    cudaStreamWaitEvent(sW2, evStart, 0);
    {
        int n4 = (EMBED * DIN) / 4;
        cvt_h<<<(n4 + 255) / 256, 256, 0, sW2>>>(o_proj_w, w2h, n4);
        cudaEventRecord(evW2, sW2);
    }

    // critical path: split u (hi/lo), convert w1
    {
        int n4 = (M * EMBED) / 4;
        split2h<<<(n4 + 255) / 256, 256>>>(u, uh, ul, n4);
        n4 = (DPROJ * EMBED) / 4;
        cvt_h<<<(n4 + 255) / 256, 256>>>(in_proj_w, w1h, n4);
    }
    // 1) in_proj: zx = u @ W1^T  (HMMA fp16x2, 128x256 tile)
    hgemm2<<<dim3((DPROJ + HBN - 1) / HBN, M / HBM), 512, SMEM_GEMM>>>(
        M, DPROJ, EMBED, uh, ul, w1h, zx);
    cudaEventRecord(evZX, 0);

    // side: fused dt softplus + cumsum (depends only on zx)
    cudaStreamWaitEvent(sCS, evZX, 0);
    cumsum_k<<<NBC * NH, 32, 0, sCS>>>(A_log, dt_bias);
    cudaEventRecord(evCum, sCS);

    // 2) causal depthwise conv + silu (smem-tiled)
    conv_silu_k<<<dim3(CONVDIM / 64, LL / 128, BB), 256>>>(conv_w, conv_b);
    cudaEventRecord(evXBC, 0);

    // side: scores (depends only on xbc; feeds only ych)
    cudaStreamWaitEvent(sSC, evXBC, 0);
    scores_k<<<dim3(4, 4, NBC), 256, 0, sSC>>>();
    cudaEventRecord(evScores, sSC);

    // critical path: states (needs cumsum) -> scan
    cudaStreamWaitEvent(0, evCum, 0);
    states_k<<<NBC * NH, 256>>>();
    scan_k<<<dim3(BB * NH, 16), 512>>>();

    // join scores, then ych
    cudaStreamWaitEvent(0, evScores, 0);
    ych_k<<<dim3(4, NH, NBC), 256>>>(D_skip, norm_w);

    // join w2 convert, then o_proj
    cudaStreamWaitEvent(0, evW2, 0);
    hgemm2<<<dim3(EMBED / HBN, M / HBM), 512, SMEM_GEMM>>>(
        M, EMBED, DIN, ynh, ynl, w2h, out);
}